// round 1
// baseline (speedup 1.0000x reference)
#include <cuda_runtime.h>
#include <math.h>

#define B_  4
#define T_  32
#define C_  128
#define HW_ 1024
#define N_  4096
#define GD_ 64
#define M_  (T_*N_)      // 131072 rows, r = t*N_ + n
#define F_  512

// ---------------- scratch (device globals; no allocation) ----------------
static __device__ float g_mu[M_];
static __device__ float g_rs[M_];
static __device__ float g_q [(size_t)M_*C_];
static __device__ float g_k [(size_t)M_*C_];
static __device__ float g_v [(size_t)M_*C_];
static __device__ float g_at[(size_t)M_*C_];

// ---------------- kernel 1: ln1 stats per row (n,t) ----------------------
__global__ __launch_bounds__(256) void k_stats(const float* __restrict__ x)
{
    const int bt = blockIdx.x;            // b*T_ + t
    const int b = bt / T_, t = bt % T_;
    const float* xp = x + (size_t)bt * C_ * HW_;
    const int tid = threadIdx.x;
    float s[4]  = {0.f,0.f,0.f,0.f};
    float s2[4] = {0.f,0.f,0.f,0.f};
    for (int c = 0; c < C_; c++) {
        const float* row = xp + (size_t)c * HW_;
        #pragma unroll
        for (int j = 0; j < 4; j++) {
            float v = row[tid + 256*j];
            s[j] += v; s2[j] += v*v;
        }
    }
    #pragma unroll
    for (int j = 0; j < 4; j++) {
        int hw = tid + 256*j;
        float mu  = s[j] * (1.0f/C_);
        float var = s2[j] * (1.0f/C_) - mu*mu;
        int r = t*N_ + b*HW_ + hw;
        g_mu[r] = mu;
        g_rs[r] = rsqrtf(var + 1e-5f);
    }
}

// ---------------- kernel 2: QKV GEMM (transpose fused into A loads) ------
__global__ __launch_bounds__(256) void k_qkv(
    const float* __restrict__ x, const float* __restrict__ gdn,
    const float* __restrict__ Wq, const float* __restrict__ bq,
    const float* __restrict__ Wk, const float* __restrict__ bk,
    const float* __restrict__ Wv, const float* __restrict__ bv)
{
    __shared__ __align__(16) float sA[64*33];
    __shared__ __align__(16) float sB[32*132];
    const int y  = blockIdx.y;                 // 0:q 1:k 2:v
    const int r0 = blockIdx.x * 64;
    const int t  = r0 / N_;
    const int n0 = r0 % N_;
    const int b  = n0 / HW_;
    const int hw0 = n0 % HW_;
    const float* Wsel = (y == 0) ? Wq : ((y == 1) ? Wk : Wv);
    const float* bsel = (y == 0) ? bq : ((y == 1) ? bk : bv);
    float* outp = (y == 0) ? g_q : ((y == 1) ? g_k : g_v);
    const int KT = (y == 2) ? 4 : 6;           // v: K=128, q/k: K=192
    const int tid = threadIdx.x;
    const int tx = tid & 15, ty = tid >> 4;
    const float* xbt = x   + (size_t)(b*T_ + t) * C_ * HW_;
    const float* gbt = gdn + (size_t)(b*T_ + t) * GD_;

    float acc[4][8];
    #pragma unroll
    for (int i = 0; i < 4; i++)
        #pragma unroll
        for (int j = 0; j < 8; j++) acc[i][j] = 0.f;

    const int rlA = tid & 63,  kbA = tid >> 6;
    const int colB = tid & 127, kbB = tid >> 7;

    for (int kt = 0; kt < KT; kt++) {
        #pragma unroll
        for (int j = 0; j < 8; j++) {
            int kk = kbA + 4*j;
            int c  = kt*32 + kk;
            float v = (c < C_) ? xbt[(size_t)c*HW_ + hw0 + rlA]
                               : gbt[c - C_];
            sA[rlA*33 + kk] = v;
        }
        #pragma unroll
        for (int jj = 0; jj < 16; jj++) {
            int kk = kbB + 2*jj;
            sB[kk*132 + colB] = Wsel[(size_t)(kt*32 + kk)*C_ + colB];
        }
        __syncthreads();
        #pragma unroll
        for (int kk = 0; kk < 32; kk++) {
            float aa[4];
            #pragma unroll
            for (int i = 0; i < 4; i++) aa[i] = sA[(ty*4+i)*33 + kk];
            float4 b0 = *(const float4*)&sB[kk*132 + tx*8];
            float4 b1 = *(const float4*)&sB[kk*132 + tx*8 + 4];
            float bb[8] = {b0.x,b0.y,b0.z,b0.w,b1.x,b1.y,b1.z,b1.w};
            #pragma unroll
            for (int i = 0; i < 4; i++)
                #pragma unroll
                for (int j = 0; j < 8; j++)
                    acc[i][j] += aa[i]*bb[j];
        }
        __syncthreads();
    }
    #pragma unroll
    for (int i = 0; i < 4; i++) {
        int r = r0 + ty*4 + i;
        #pragma unroll
        for (int j = 0; j < 8; j++) {
            int col = tx*8 + j;
            float val = acc[i][j] + bsel[col];
            if (y < 2) val = (val > 0.f) ? (val + 1.f) : expf(val); // elu+1
            else       val *= (1.0f/T_);                            // v/T
            outp[(size_t)r*C_ + col] = val;
        }
    }
}

// ---------------- kernel 3: linear attention, one block per n ------------
__global__ __launch_bounds__(128) void k_attn()
{
    __shared__ __align__(16) float pool[4224*2 + 256];
    float* pK    = pool;            // [32][132]: K, then Q
    float* pV    = pool + 4224;     // [32][132]: V, then KV [4][32][33]
    float* sKsum = pool + 8448;     // 128
    float* sZ    = pool + 8448 + 128; // 128 : [t][h]
    const int n = blockIdx.x;
    const int tid = threadIdx.x;

    for (int s = 0; s < 32; s++) {
        pK[s*132 + tid] = g_k[(size_t)(s*N_ + n)*C_ + tid];
        pV[s*132 + tid] = g_v[(size_t)(s*N_ + n)*C_ + tid];
    }
    __syncthreads();

    const int h = tid >> 5, d = tid & 31;   // tid == h*32 + d
    float kv[32];
    #pragma unroll
    for (int vv = 0; vv < 32; vv++) kv[vv] = 0.f;
    float ks = 0.f;
    for (int s = 0; s < 32; s++) {
        float kd = pK[s*132 + h*32 + d];
        ks += kd;
        const float* vrow = &pV[s*132 + h*32];
        #pragma unroll
        for (int vv = 0; vv < 32; vv += 4) {
            float4 vf = *(const float4*)&vrow[vv];
            kv[vv+0] += kd * vf.x;
            kv[vv+1] += kd * vf.y;
            kv[vv+2] += kd * vf.z;
            kv[vv+3] += kd * vf.w;
        }
    }
    __syncthreads();
    // KV -> smem [h][d][vv] with pad-33 (conflict-free both ways); Ksum; Q
    #pragma unroll
    for (int vv = 0; vv < 32; vv++)
        pV[h*1056 + d*33 + vv] = kv[vv];
    sKsum[tid] = ks;
    for (int s = 0; s < 32; s++)
        pK[s*132 + tid] = g_q[(size_t)(s*N_ + n)*C_ + tid];
    __syncthreads();
    // Z[t][h] = T / (Q.Ksum + eps)
    {
        int tz = tid >> 2, hz = tid & 3;
        float z = 0.f;
        #pragma unroll
        for (int dd = 0; dd < 32; dd++)
            z += pK[tz*132 + hz*32 + dd] * sKsum[hz*32 + dd];
        sZ[tz*4 + hz] = (float)T_ / (z + 1e-6f);
    }
    __syncthreads();
    // out[t][h*32+vv], thread: vv = d
    const float* kvb = &pV[h*1056];
    for (int tt = 0; tt < 32; tt++) {
        float acc = 0.f;
        const float* qrow = &pK[tt*132 + h*32];
        #pragma unroll
        for (int dd = 0; dd < 32; dd++)
            acc += qrow[dd] * kvb[dd*33 + d];
        g_at[(size_t)(tt*N_ + n)*C_ + tid] = acc * sZ[tt*4 + h];
    }
}

// ---------------- kernel 4: residual + ln2 + FFN + writeback -------------
// smem floats: sO 64*129 | sU 64*129 | sH 64*132 | sBt 32*132 | stats 256
__global__ __launch_bounds__(256) void k_ffn(
    const float* __restrict__ x,
    const float* __restrict__ l1g, const float* __restrict__ l1b,
    const float* __restrict__ l2g, const float* __restrict__ l2b,
    const float* __restrict__ W1,  const float* __restrict__ b1f,
    const float* __restrict__ W2,  const float* __restrict__ b2f,
    float* __restrict__ out)
{
    extern __shared__ __align__(16) float sm[];
    float* sO  = sm;           // out_full tile [64][129]
    float* sU  = sm + 8256;    // ln2 tile      [64][129]
    float* sH  = sm + 16512;   // gelu chunk    [64][132]
    float* sBt = sm + 24960;   // weight tile   [32][132]
    float* sM1 = sm + 29184;
    float* sR1 = sm + 29248;
    float* sM2 = sm + 29312;
    float* sR2 = sm + 29376;

    const int tid = threadIdx.x;
    const int r0 = blockIdx.x * 64;
    const int t  = r0 / N_,  n0 = r0 % N_;
    const int b  = n0 / HW_, hw0 = n0 % HW_;

    if (tid < 64) { sM1[tid] = g_mu[r0+tid]; sR1[tid] = g_rs[r0+tid]; }
    {   // attn tile load, c-major coalesced
        const int c4 = (tid & 31) * 4;
        const int rb = tid >> 5;
        #pragma unroll
        for (int j = 0; j < 8; j++) {
            int row = rb + 8*j;
            float4 a = *(const float4*)&g_at[(size_t)(r0+row)*C_ + c4];
            sO[row*129 + c4+0] = a.x;
            sO[row*129 + c4+1] = a.y;
            sO[row*129 + c4+2] = a.z;
            sO[row*129 + c4+3] = a.w;
        }
    }
    __syncthreads();
    const int rl = tid & 63, cb = tid >> 6;
    {   // + ln1(x), x gather n-major coalesced
        const float mu = sM1[rl], rs = sR1[rl];
        const float* xb = x + (size_t)(b*T_+t)*C_*HW_ + hw0 + rl;
        for (int c = cb; c < C_; c += 4) {
            float xv = xb[(size_t)c*HW_];
            sO[rl*129 + c] += (xv - mu)*rs*l1g[c] + l1b[c];
        }
    }
    __syncthreads();
    if (tid < 64) {   // ln2 stats
        float s = 0.f, s2 = 0.f;
        for (int c = 0; c < C_; c++) { float v = sO[tid*129+c]; s += v; s2 += v*v; }
        float mu = s*(1.f/C_);
        sM2[tid] = mu;
        sR2[tid] = rsqrtf(s2*(1.f/C_) - mu*mu + 1e-5f);
    }
    __syncthreads();
    {   // sU = ln2(sO)
        const float mu = sM2[rl], rs = sR2[rl];
        for (int c = cb; c < C_; c += 4)
            sU[rl*129 + c] = (sO[rl*129+c] - mu)*rs*l2g[c] + l2b[c];
    }
    __syncthreads();

    const int tx = tid & 15, ty = tid >> 4;
    const int colB = tid & 127, kbB = tid >> 7;
    float acc2[4][8];
    #pragma unroll
    for (int i = 0; i < 4; i++)
        #pragma unroll
        for (int j = 0; j < 8; j++) acc2[i][j] = 0.f;

    for (int jc = 0; jc < 4; jc++) {       // 4 chunks of 128 FFN cols
        float acc1[4][8];
        #pragma unroll
        for (int i = 0; i < 4; i++)
            #pragma unroll
            for (int j = 0; j < 8; j++) acc1[i][j] = 0.f;
        // GEMM1: sU(64x128) @ W1[:, jc*128:+128]
        for (int kt = 0; kt < 4; kt++) {
            #pragma unroll
            for (int jj = 0; jj < 16; jj++) {
                int kk = kbB + 2*jj;
                sBt[kk*132 + colB] = W1[(size_t)(kt*32+kk)*F_ + jc*128 + colB];
            }
            __syncthreads();
            #pragma unroll
            for (int kk = 0; kk < 32; kk++) {
                float aa[4];
                #pragma unroll
                for (int i = 0; i < 4; i++) aa[i] = sU[(ty*4+i)*129 + kt*32 + kk];
                float4 b0 = *(const float4*)&sBt[kk*132 + tx*8];
                float4 b1 = *(const float4*)&sBt[kk*132 + tx*8 + 4];
                float bb[8] = {b0.x,b0.y,b0.z,b0.w,b1.x,b1.y,b1.z,b1.w};
                #pragma unroll
                for (int i = 0; i < 4; i++)
                    #pragma unroll
                    for (int j = 0; j < 8; j++)
                        acc1[i][j] += aa[i]*bb[j];
            }
            __syncthreads();
        }
        // bias + exact gelu -> sH
        #pragma unroll
        for (int i = 0; i < 4; i++)
            #pragma unroll
            for (int j = 0; j < 8; j++) {
                int row = ty*4+i, col = tx*8+j;
                float hv = acc1[i][j] + b1f[jc*128 + col];
                hv = 0.5f*hv*(1.f + erff(hv*0.70710678118f));
                sH[row*132 + col] = hv;
            }
        // GEMM2 partial: sH(64x128) @ W2[jc*128:+128, :]
        for (int kt = 0; kt < 4; kt++) {
            #pragma unroll
            for (int jj = 0; jj < 16; jj++) {
                int kk = kbB + 2*jj;
                sBt[kk*132 + colB] = W2[(size_t)(jc*128 + kt*32 + kk)*C_ + colB];
            }
            __syncthreads();
            #pragma unroll
            for (int kk = 0; kk < 32; kk++) {
                float aa[4];
                #pragma unroll
                for (int i = 0; i < 4; i++) aa[i] = sH[(ty*4+i)*132 + kt*32 + kk];
                float4 b0 = *(const float4*)&sBt[kk*132 + tx*8];
                float4 b1 = *(const float4*)&sBt[kk*132 + tx*8 + 4];
                float bb[8] = {b0.x,b0.y,b0.z,b0.w,b1.x,b1.y,b1.z,b1.w};
                #pragma unroll
                for (int i = 0; i < 4; i++)
                    #pragma unroll
                    for (int j = 0; j < 8; j++)
                        acc2[i][j] += aa[i]*bb[j];
            }
            __syncthreads();
        }
    }
    // final residual into sO
    #pragma unroll
    for (int i = 0; i < 4; i++)
        #pragma unroll
        for (int j = 0; j < 8; j++) {
            int row = ty*4+i, col = tx*8+j;
            sO[row*129 + col] += acc2[i][j] + b2f[col];
        }
    __syncthreads();
    {   // transposed writeback, n-major coalesced
        float* ob = out + (size_t)(b*T_+t)*C_*HW_ + hw0 + rl;
        for (int c = cb; c < C_; c += 4)
            ob[(size_t)c*HW_] = sO[rl*129 + c];
    }
}

// ---------------- launch --------------------------------------------------
extern "C" void kernel_launch(void* const* d_in, const int* in_sizes, int n_in,
                              void* d_out, int out_size)
{
    (void)in_sizes; (void)n_in; (void)out_size;
    const float* x   = (const float*)d_in[0];
    const float* gd  = (const float*)d_in[1];
    const float* Wq  = (const float*)d_in[2];
    const float* bq  = (const float*)d_in[3];
    const float* Wk  = (const float*)d_in[4];
    const float* bk  = (const float*)d_in[5];
    const float* Wv  = (const float*)d_in[6];
    const float* bv  = (const float*)d_in[7];
    const float* l1g = (const float*)d_in[8];
    const float* l1b = (const float*)d_in[9];
    const float* l2g = (const float*)d_in[10];
    const float* l2b = (const float*)d_in[11];
    const float* W1  = (const float*)d_in[12];
    const float* b1  = (const float*)d_in[13];
    const float* W2  = (const float*)d_in[14];
    const float* b2  = (const float*)d_in[15];
    float* out = (float*)d_out;

    const int smemFfn = 29440 * 4;  // 117,760 B dynamic
    cudaFuncSetAttribute(k_ffn, cudaFuncAttributeMaxDynamicSharedMemorySize, smemFfn);

    k_stats<<<B_*T_, 256>>>(x);
    k_qkv  <<<dim3(M_/64, 3), 256>>>(x, gd, Wq, bq, Wk, bk, Wv, bv);
    k_attn <<<N_, 128>>>();
    k_ffn  <<<M_/64, 256, smemFfn>>>(x, l1g, l1b, l2g, l2b, W1, b1, W2, b2, out);
}

// round 4
// speedup vs baseline: 2.4551x; 2.4551x over previous
#include <cuda_runtime.h>
#include <math.h>
#include <stdint.h>

#define B_  4
#define T_  32
#define C_  128
#define HW_ 1024
#define N_  4096
#define GD_ 64
#define M_  (T_*N_)      // 131072 rows, r = t*N_ + n
#define F_  512

// ---------------- scratch (device globals; no allocation) ----------------
static __device__ float g_mu[M_];
static __device__ float g_rs[M_];
static __device__ float g_q [(size_t)M_*C_];
static __device__ float g_k [(size_t)M_*C_];
static __device__ float g_v [(size_t)M_*C_];
static __device__ float g_at[(size_t)M_*C_];

// ---------------- helpers -------------------------------------------------
__device__ __forceinline__ float rna(float f){
    float r; asm("cvt.rna.tf32.f32 %0, %1;" : "=f"(r) : "f"(f)); return r;
}
__device__ __forceinline__ void mma8(float* d, const uint32_t* a,
                                     uint32_t b0, uint32_t b1){
    asm volatile(
        "mma.sync.aligned.m16n8k8.row.col.f32.tf32.tf32.f32 "
        "{%0,%1,%2,%3}, {%4,%5,%6,%7}, {%8,%9}, {%0,%1,%2,%3};"
        : "+f"(d[0]), "+f"(d[1]), "+f"(d[2]), "+f"(d[3])
        : "r"(a[0]), "r"(a[1]), "r"(a[2]), "r"(a[3]), "r"(b0), "r"(b1));
}

// ---------------- kernel 1: ln1 stats per row (n,t) ----------------------
__global__ __launch_bounds__(256) void k_stats(const float* __restrict__ x)
{
    const int bt = blockIdx.x;
    const int b = bt / T_, t = bt % T_;
    const float* xp = x + (size_t)bt * C_ * HW_;
    const int tid = threadIdx.x;
    float s[4]  = {0.f,0.f,0.f,0.f};
    float s2[4] = {0.f,0.f,0.f,0.f};
    for (int c = 0; c < C_; c++) {
        const float* row = xp + (size_t)c * HW_;
        #pragma unroll
        for (int j = 0; j < 4; j++) {
            float v = row[tid + 256*j];
            s[j] += v; s2[j] += v*v;
        }
    }
    #pragma unroll
    for (int j = 0; j < 4; j++) {
        int hw = tid + 256*j;
        float mu  = s[j] * (1.0f/C_);
        float var = s2[j] * (1.0f/C_) - mu*mu;
        int r = t*N_ + b*HW_ + hw;
        g_mu[r] = mu;
        g_rs[r] = rsqrtf(var + 1e-5f);
    }
}

// ---------------- kernel 2: QKV GEMM via mma.sync tf32 -------------------
// 512 threads, 16 warps (8x2). Tile: 128 rows x 128 cols, K=192 (q,k) / 128 (v).
// smem: sA[128][196], sW[128][196]
#define QP_ 196
__global__ __launch_bounds__(512) void k_qkv_tc(
    const float* __restrict__ x, const float* __restrict__ gdn,
    const float* __restrict__ Wq, const float* __restrict__ bq,
    const float* __restrict__ Wk, const float* __restrict__ bk,
    const float* __restrict__ Wv, const float* __restrict__ bv)
{
    extern __shared__ float sm[];
    float* sA = sm;
    float* sW = sm + 128*QP_;

    const int y  = blockIdx.y;                 // 0:q 1:k 2:v
    const int r0 = blockIdx.x * 128;
    const int t  = r0 / N_;
    const int n0 = r0 % N_;
    const int b  = n0 / HW_;
    const int hw0 = n0 % HW_;
    const float* Wsel = (y == 0) ? Wq : ((y == 1) ? Wk : Wv);
    const float* bsel = (y == 0) ? bq : ((y == 1) ? bk : bv);
    float* outp = (y == 0) ? g_q : ((y == 1) ? g_k : g_v);
    const int KT = (y == 2) ? 128 : 192;

    const int tid = threadIdx.x;
    const int lane = tid & 31, wid = tid >> 5;
    const int wm = wid >> 1, wn = wid & 1;
    const int gid = lane >> 2, tig = lane & 3;
    const int arow = wm*16 + gid;

    const float* xbt = x   + (size_t)(b*T_ + t) * C_ * HW_;
    const float* gbt = gdn + (size_t)(b*T_ + t) * GD_;

    // fill A (rows = hw, cols = channel; transpose fused, tf32-rounded)
    {
        const int rl = tid & 127, cq = tid >> 7;
        for (int p = 0; p < KT/4; p++) {
            int c = cq + 4*p;
            float v = (c < C_) ? xbt[(size_t)c*HW_ + hw0 + rl] : gbt[c - C_];
            sA[rl*QP_ + c] = rna(v);
        }
        // fill W: sW[n][k] = W[k][n]
        for (int p = 0; p < KT/4; p++) {
            int k = cq + 4*p;
            sW[rl*QP_ + k] = rna(Wsel[(size_t)k*C_ + rl]);
        }
    }
    __syncthreads();

    float acc[8][4];
    #pragma unroll
    for (int j = 0; j < 8; j++)
        #pragma unroll
        for (int q = 0; q < 4; q++) acc[j][q] = 0.f;

    const int nksteps = KT >> 3;
    #pragma unroll 4
    for (int ks = 0; ks < nksteps; ks++) {
        const int k0 = ks*8;
        uint32_t a[4];
        a[0] = __float_as_uint(sA[arow*QP_ + k0 + tig]);
        a[1] = __float_as_uint(sA[(arow+8)*QP_ + k0 + tig]);
        a[2] = __float_as_uint(sA[arow*QP_ + k0 + tig + 4]);
        a[3] = __float_as_uint(sA[(arow+8)*QP_ + k0 + tig + 4]);
        #pragma unroll
        for (int j = 0; j < 8; j++) {
            const int nb = (wn*64 + j*8 + gid)*QP_ + k0 + tig;
            uint32_t b0 = __float_as_uint(sW[nb]);
            uint32_t b1 = __float_as_uint(sW[nb + 4]);
            mma8(acc[j], a, b0, b1);
        }
    }
    __syncthreads();
    // stage to sA (QP_ even, col even -> float2 aligned)
    #pragma unroll
    for (int j = 0; j < 8; j++) {
        const int col = wn*64 + j*8 + 2*tig;
        *(float2*)&sA[arow*QP_ + col]     = make_float2(acc[j][0], acc[j][1]);
        *(float2*)&sA[(arow+8)*QP_ + col] = make_float2(acc[j][2], acc[j][3]);
    }
    __syncthreads();
    // epilogue: bias + activation, coalesced write
    {
        const int col = tid & 127, rq = tid >> 7;
        const float bb = bsel[col];
        for (int i = 0; i < 32; i++) {
            int row = rq + 4*i;
            float v = sA[row*QP_ + col] + bb;
            if (y < 2) v = (v > 0.f) ? (v + 1.f) : expf(v);
            else       v *= (1.0f/T_);
            outp[(size_t)(r0+row)*C_ + col] = v;
        }
    }
}

// ---------------- kernel 3: linear attention (unchanged) -----------------
__global__ __launch_bounds__(128) void k_attn()
{
    __shared__ __align__(16) float pool[4224*2 + 256];
    float* pK    = pool;
    float* pV    = pool + 4224;
    float* sKsum = pool + 8448;
    float* sZ    = pool + 8448 + 128;
    const int n = blockIdx.x;
    const int tid = threadIdx.x;

    for (int s = 0; s < 32; s++) {
        pK[s*132 + tid] = g_k[(size_t)(s*N_ + n)*C_ + tid];
        pV[s*132 + tid] = g_v[(size_t)(s*N_ + n)*C_ + tid];
    }
    __syncthreads();

    const int h = tid >> 5, d = tid & 31;
    float kv[32];
    #pragma unroll
    for (int vv = 0; vv < 32; vv++) kv[vv] = 0.f;
    float ks = 0.f;
    for (int s = 0; s < 32; s++) {
        float kd = pK[s*132 + h*32 + d];
        ks += kd;
        const float* vrow = &pV[s*132 + h*32];
        #pragma unroll
        for (int vv = 0; vv < 32; vv += 4) {
            float4 vf = *(const float4*)&vrow[vv];
            kv[vv+0] += kd * vf.x;
            kv[vv+1] += kd * vf.y;
            kv[vv+2] += kd * vf.z;
            kv[vv+3] += kd * vf.w;
        }
    }
    __syncthreads();
    #pragma unroll
    for (int vv = 0; vv < 32; vv++)
        pV[h*1056 + d*33 + vv] = kv[vv];
    sKsum[tid] = ks;
    for (int s = 0; s < 32; s++)
        pK[s*132 + tid] = g_q[(size_t)(s*N_ + n)*C_ + tid];
    __syncthreads();
    {
        int tz = tid >> 2, hz = tid & 3;
        float z = 0.f;
        #pragma unroll
        for (int dd = 0; dd < 32; dd++)
            z += pK[tz*132 + hz*32 + dd] * sKsum[hz*32 + dd];
        sZ[tz*4 + hz] = (float)T_ / (z + 1e-6f);
    }
    __syncthreads();
    const float* kvb = &pV[h*1056];
    for (int tt = 0; tt < 32; tt++) {
        float acc = 0.f;
        const float* qrow = &pK[tt*132 + h*32];
        #pragma unroll
        for (int dd = 0; dd < 32; dd++)
            acc += qrow[dd] * kvb[dd*33 + d];
        g_at[(size_t)(tt*N_ + n)*C_ + tid] = acc * sZ[tt*4 + h];
    }
}

// ---------------- kernel 4: FFN via mma.sync tf32 ------------------------
__global__ __launch_bounds__(512) void k_ffn_tc(
    const float* __restrict__ x,
    const float* __restrict__ l1g, const float* __restrict__ l1b,
    const float* __restrict__ l2g, const float* __restrict__ l2b,
    const float* __restrict__ W1,  const float* __restrict__ b1f,
    const float* __restrict__ W2,  const float* __restrict__ b2f,
    float* __restrict__ out)
{
    extern __shared__ float sm[];
    float* sU  = sm;
    float* sW  = sm + 16896;
    float* sOH = sm + 33792;
    float* sM2 = sm + 50688;
    float* sR2 = sm + 50816;

    const int tid = threadIdx.x;
    const int lane = tid & 31, wid = tid >> 5;
    const int wm = wid >> 1, wn = wid & 1;
    const int gid = lane >> 2, tig = lane & 3;
    const int arow = wm*16 + gid;

    const int r0 = blockIdx.x * 128;
    const int t  = r0 / N_,  n0 = r0 % N_;
    const int b  = n0 / HW_, hw0 = n0 % HW_;

    // ---- O = attn + ln1(x) into sOH (pad 129) ----
    {
        const int cc = (tid & 31) * 4;
        const int rb = tid >> 5;               // 0..15
        for (int j = 0; j < 8; j++) {
            int row = rb + 16*j;
            float4 a = *(const float4*)&g_at[(size_t)(r0+row)*C_ + cc];
            float* o = &sOH[row*129 + cc];
            o[0]=a.x; o[1]=a.y; o[2]=a.z; o[3]=a.w;
        }
    }
    __syncthreads();
    {
        const int rl = tid & 127, cq = tid >> 7;
        const float mu = g_mu[r0+rl], rs = g_rs[r0+rl];
        const float* xb = x + (size_t)(b*T_+t)*C_*HW_ + hw0 + rl;
        for (int c = cq; c < C_; c += 4)
            sOH[rl*129 + c] += (xb[(size_t)c*HW_] - mu)*rs*l1g[c] + l1b[c];
    }
    __syncthreads();
    if (tid < 128) {   // ln2 stats (conflict-free: bank = tid + c)
        float s = 0.f, s2 = 0.f;
        for (int c = 0; c < C_; c++) { float v = sOH[tid*129+c]; s += v; s2 += v*v; }
        float mu = s*(1.f/C_);
        sM2[tid] = mu;
        sR2[tid] = rsqrtf(s2*(1.f/C_) - mu*mu + 1e-5f);
    }
    __syncthreads();
    {   // sU = tf32(ln2(O))
        const int rl = tid & 127, cq = tid >> 7;
        const float mu = sM2[rl], rs = sR2[rl];
        for (int c = cq; c < C_; c += 4)
            sU[rl*132 + c] = rna((sOH[rl*129+c] - mu)*rs*l2g[c] + l2b[c]);
    }
    __syncthreads();

    // acc2 = O fragment + b2 (residual + final bias pre-loaded)
    float acc2[8][4];
    #pragma unroll
    for (int j = 0; j < 8; j++) {
        const int col = wn*64 + j*8 + 2*tig;
        acc2[j][0] = sOH[arow*129 + col]       + b2f[col];
        acc2[j][1] = sOH[arow*129 + col + 1]   + b2f[col+1];
        acc2[j][2] = sOH[(arow+8)*129 + col]   + b2f[col];
        acc2[j][3] = sOH[(arow+8)*129 + col+1] + b2f[col+1];
    }
    // sOH reusable as gelu buffer (pad 132) after next sync

    const int rl = tid & 127, kq = tid >> 7;
    for (int jc = 0; jc < 4; jc++) {
        // fill W1 chunk: sW[n][k] = W1[k][jc*128+n]
        for (int p = 0; p < 32; p++) {
            int k = kq + 4*p;
            sW[rl*132 + k] = rna(W1[(size_t)k*F_ + jc*128 + rl]);
        }
        __syncthreads();

        float acc1[8][4];
        #pragma unroll
        for (int j = 0; j < 8; j++) {
            const int col = jc*128 + wn*64 + j*8 + 2*tig;
            acc1[j][0] = b1f[col];   acc1[j][1] = b1f[col+1];
            acc1[j][2] = acc1[j][0]; acc1[j][3] = acc1[j][1];
        }
        #pragma unroll 4
        for (int ks = 0; ks < 16; ks++) {
            const int k0 = ks*8;
            uint32_t a[4];
            a[0] = __float_as_uint(sU[arow*132 + k0 + tig]);
            a[1] = __float_as_uint(sU[(arow+8)*132 + k0 + tig]);
            a[2] = __float_as_uint(sU[arow*132 + k0 + tig + 4]);
            a[3] = __float_as_uint(sU[(arow+8)*132 + k0 + tig + 4]);
            #pragma unroll
            for (int j = 0; j < 8; j++) {
                const int nb = (wn*64 + j*8 + gid)*132 + k0 + tig;
                mma8(acc1[j], a, __float_as_uint(sW[nb]),
                                  __float_as_uint(sW[nb + 4]));
            }
        }
        // gelu -> sOH (pad 132, even -> float2 aligned), tf32-rounded
        #pragma unroll
        for (int j = 0; j < 8; j++) {
            const int col = wn*64 + j*8 + 2*tig;
            float g0 = acc1[j][0], g1 = acc1[j][1];
            float g2 = acc1[j][2], g3 = acc1[j][3];
            g0 = rna(0.5f*g0*(1.f + erff(g0*0.70710678118f)));
            g1 = rna(0.5f*g1*(1.f + erff(g1*0.70710678118f)));
            g2 = rna(0.5f*g2*(1.f + erff(g2*0.70710678118f)));
            g3 = rna(0.5f*g3*(1.f + erff(g3*0.70710678118f)));
            *(float2*)&sOH[arow*132 + col]     = make_float2(g0, g1);
            *(float2*)&sOH[(arow+8)*132 + col] = make_float2(g2, g3);
        }
        __syncthreads();
        // fill W2 chunk: sW[n][k] = W2[jc*128+k][n]
        for (int p = 0; p < 32; p++) {
            int k = kq + 4*p;
            sW[rl*132 + k] = rna(W2[(size_t)(jc*128 + k)*C_ + rl]);
        }
        __syncthreads();
        // GEMM2: acc2 += H @ W2chunk
        #pragma unroll 4
        for (int ks = 0; ks < 16; ks++) {
            const int k0 = ks*8;
            uint32_t a[4];
            a[0] = __float_as_uint(sOH[arow*132 + k0 + tig]);
            a[1] = __float_as_uint(sOH[(arow+8)*132 + k0 + tig]);
            a[2] = __float_as_uint(sOH[arow*132 + k0 + tig + 4]);
            a[3] = __float_as_uint(sOH[(arow+8)*132 + k0 + tig + 4]);
            #pragma unroll
            for (int j = 0; j < 8; j++) {
                const int nb = (wn*64 + j*8 + gid)*132 + k0 + tig;
                mma8(acc2[j], a, __float_as_uint(sW[nb]),
                                  __float_as_uint(sW[nb + 4]));
            }
        }
        __syncthreads();
    }

    // stage acc2 -> sOH (pad 129) -- SCALAR stores (129 odd: float2 would misalign)
    #pragma unroll
    for (int j = 0; j < 8; j++) {
        const int col = wn*64 + j*8 + 2*tig;
        sOH[arow*129 + col]       = acc2[j][0];
        sOH[arow*129 + col + 1]   = acc2[j][1];
        sOH[(arow+8)*129 + col]   = acc2[j][2];
        sOH[(arow+8)*129 + col+1] = acc2[j][3];
    }
    __syncthreads();
    // transposed coalesced writeback
    {
        float* op = out + (size_t)(b*T_+t)*C_*HW_ + hw0 + rl;
        for (int c = kq; c < C_; c += 4)
            op[(size_t)c*HW_] = sOH[rl*129 + c];
    }
}

// ---------------- launch --------------------------------------------------
extern "C" void kernel_launch(void* const* d_in, const int* in_sizes, int n_in,
                              void* d_out, int out_size)
{
    (void)in_sizes; (void)n_in; (void)out_size;
    const float* x   = (const float*)d_in[0];
    const float* gd  = (const float*)d_in[1];
    const float* Wq  = (const float*)d_in[2];
    const float* bq  = (const float*)d_in[3];
    const float* Wk  = (const float*)d_in[4];
    const float* bk  = (const float*)d_in[5];
    const float* Wv  = (const float*)d_in[6];
    const float* bv  = (const float*)d_in[7];
    const float* l1g = (const float*)d_in[8];
    const float* l1b = (const float*)d_in[9];
    const float* l2g = (const float*)d_in[10];
    const float* l2b = (const float*)d_in[11];
    const float* W1  = (const float*)d_in[12];
    const float* b1  = (const float*)d_in[13];
    const float* W2  = (const float*)d_in[14];
    const float* b2  = (const float*)d_in[15];
    float* out = (float*)d_out;

    const int smemQkv = 2*128*QP_*4;             // 200,704 B
    const int smemFfn = (50816+128)*4;           // 203,776 B
    cudaFuncSetAttribute(k_qkv_tc, cudaFuncAttributeMaxDynamicSharedMemorySize, smemQkv);
    cudaFuncSetAttribute(k_ffn_tc, cudaFuncAttributeMaxDynamicSharedMemorySize, smemFfn);

    k_stats <<<B_*T_, 256>>>(x);
    k_qkv_tc<<<dim3(M_/128, 3), 512, smemQkv>>>(x, gd, Wq, bq, Wk, bk, Wv, bv);
    k_attn  <<<N_, 128>>>();
    k_ffn_tc<<<M_/128, 512, smemFfn>>>(x, l1g, l1b, l2g, l2b, W1, b1, W2, b2, out);
}